// round 14
// baseline (speedup 1.0000x reference)
#include <cuda_runtime.h>

#define BB 8
#define SS 4096
#define NN 32
#define HH 32
#define DD 64
#define OO 32
#define ROWS (BB*SS)        // 32768
#define LN_EPS 1e-5f
#define FULLMASK 0xffffffffu

// Block = 128 threads = 4 warps; each warp handles 4 consecutive rows.
// Block covers 16 consecutive rows. Stage 1: lane = neighbor for stats,
// lane = dim for accumulate. GEMV stages: weights LDS amortized over 4 rows,
// x-broadcasts packed as float4 (one wavefront serves all 4 rows).
__global__ __launch_bounds__(128, 4) void fused_gnn(
    const float* __restrict__ expr,        // (B,S)
    const float* __restrict__ neighbors,   // (B,N,S)
    const float* __restrict__ edge,        // (B,S,N)
    const unsigned int* __restrict__ mask, // (B,S) bool widened to 4 bytes
    const float* __restrict__ nW1,         // (2,H)
    const float* __restrict__ nb1,
    const float* __restrict__ nlg,
    const float* __restrict__ nlb,
    const float* __restrict__ nW2,         // (H,H)
    const float* __restrict__ nb2,
    const float* __restrict__ sW1,         // (1,H)
    const float* __restrict__ sb1,
    const float* __restrict__ slg,
    const float* __restrict__ slb,
    const float* __restrict__ sW2,         // (H,H)
    const float* __restrict__ sb2,
    const float* __restrict__ hW1,         // (D,D)
    const float* __restrict__ hb1,
    const float* __restrict__ hlg,
    const float* __restrict__ hlb,
    const float* __restrict__ hW2,         // (D,O)
    const float* __restrict__ hb2,
    float* __restrict__ out)               // (B,S,O)
{
    __shared__ float s_nW2[HH * HH];               // 4KB
    __shared__ float s_sW2[HH * HH];               // 4KB
    __shared__ alignas(16) float s_hW1[DD * DD];   // 16KB
    __shared__ float s_hW2[DD * OO];               // 8KB
    __shared__ alignas(16) float s_nbr[NN * 20];   // 2.5KB staged neighbor tile
    __shared__ float s_selfStats[5];               // {mw, mb, c2, c1, c0}
    __shared__ float s_nStats[9];                  // neighbor LN quadratic form
    __shared__ alignas(16) float s_buf[4][512];    // 2KB scratch per warp

    const int tid  = threadIdx.x;
    const int wid  = tid >> 5;
    const int lane = tid & 31;

    // ---- cooperative weight loads (128-thread stride) ----
    for (int i = tid; i < HH * HH; i += 128) s_nW2[i] = nW2[i];
    for (int i = tid; i < HH * HH; i += 128) s_sW2[i] = sW2[i];
    for (int i = tid; i < DD * DD; i += 128) s_hW1[i] = hW1[i];
    for (int i = tid; i < DD * OO; i += 128) s_hW2[i] = hW2[i];

    // ---- warp 0: self-branch LN stats (var(ex) = c2 ex^2 + c1 ex + c0) ----
    if (wid == 0) {
        const float w  = sW1[lane];
        const float bb = sb1[lane];
        float sw = w, sb_ = bb, sww = w * w, swb = w * bb, sbb = bb * bb;
        #pragma unroll
        for (int ofs = 16; ofs >= 1; ofs >>= 1) {
            sw  += __shfl_xor_sync(FULLMASK, sw,  ofs);
            sb_ += __shfl_xor_sync(FULLMASK, sb_, ofs);
            sww += __shfl_xor_sync(FULLMASK, sww, ofs);
            swb += __shfl_xor_sync(FULLMASK, swb, ofs);
            sbb += __shfl_xor_sync(FULLMASK, sbb, ofs);
        }
        if (lane == 0) {
            const float mw = sw * (1.0f / HH), mb = sb_ * (1.0f / HH);
            s_selfStats[0] = mw;
            s_selfStats[1] = mb;
            s_selfStats[2] = fmaf(-mw, mw, sww * (1.0f / HH));
            s_selfStats[3] = 2.0f * fmaf(-mw, mb, swb * (1.0f / HH));
            s_selfStats[4] = fmaf(-mb, mb, sbb * (1.0f / HH));
        }
    }
    // ---- warp 1: neighbor-branch LN stats (quadratic form in v0,v1) ----
    if (wid == 1) {
        const float a = nW1[lane], b = nW1[HH + lane], c = nb1[lane];
        float sa = a, sb_ = b, sc = c;
        float saa = a * a, sbb = b * b, scc = c * c;
        float sab = a * b, sac = a * c, sbc = b * c;
        #pragma unroll
        for (int ofs = 16; ofs >= 1; ofs >>= 1) {
            sa  += __shfl_xor_sync(FULLMASK, sa,  ofs);
            sb_ += __shfl_xor_sync(FULLMASK, sb_, ofs);
            sc  += __shfl_xor_sync(FULLMASK, sc,  ofs);
            saa += __shfl_xor_sync(FULLMASK, saa, ofs);
            sbb += __shfl_xor_sync(FULLMASK, sbb, ofs);
            scc += __shfl_xor_sync(FULLMASK, scc, ofs);
            sab += __shfl_xor_sync(FULLMASK, sab, ofs);
            sac += __shfl_xor_sync(FULLMASK, sac, ofs);
            sbc += __shfl_xor_sync(FULLMASK, sbc, ofs);
        }
        if (lane == 0) {
            const float ma = sa * (1.0f / HH), mb = sb_ * (1.0f / HH), mc = sc * (1.0f / HH);
            s_nStats[0] = ma; s_nStats[1] = mb; s_nStats[2] = mc;
            s_nStats[3] = fmaf(-ma, ma, saa * (1.0f / HH));
            s_nStats[4] = fmaf(-mb, mb, sbb * (1.0f / HH));
            s_nStats[5] = fmaf(-mc, mc, scc * (1.0f / HH));
            s_nStats[6] = 2.0f * fmaf(-ma, mb, sab * (1.0f / HH));
            s_nStats[7] = 2.0f * fmaf(-ma, mc, sac * (1.0f / HH));
            s_nStats[8] = 2.0f * fmaf(-mb, mc, sbc * (1.0f / HH));
        }
    }

    // ---- stage neighbor tile: rows [r0, r0+16) need neighbors[b][:][s0..s0+15]
    const int r0 = blockIdx.x * 16;
    const int b  = r0 >> 12;
    const int s0 = r0 & (SS - 1);
    {
        const int n  = tid >> 2;              // 0..31
        const int sl = (tid & 3) * 4;         // 0,4,8,12
        const float4 v = *(const float4*)(neighbors + (size_t)b * (NN * SS)
                                          + (size_t)n * SS + s0 + sl);
        *(float4*)&s_nbr[n * 20 + sl] = v;
    }
    __syncthreads();

    const int rowBase = r0 + wid * 4;         // rows rowBase..rowBase+3
    float* buf = s_buf[wid];

    // ============== stage 1a: per-neighbor LN stats (lane = neighbor) ======
    {
        // one LDS.128: (v0 for this lane's neighbor, rows 0..3) — stride-20
        // rows → 8-lane phases hit distinct banks, conflict-free.
        const float4 v0v = *(const float4*)&s_nbr[lane * 20 + wid * 4];
        const float v0r[4] = {v0v.x, v0v.y, v0v.z, v0v.w};
        const float ma = s_nStats[0], mb_ = s_nStats[1], mc = s_nStats[2];
        const float Caa = s_nStats[3], Cbb = s_nStats[4], Ccc = s_nStats[5];
        const float Cab2 = s_nStats[6], Cac2 = s_nStats[7], Cbc2 = s_nStats[8];
        #pragma unroll
        for (int rr = 0; rr < 4; rr++) {
            const float v0 = v0r[rr];
            const float v1 = edge[(size_t)(rowBase + rr) * NN + lane];
            const float m  = fmaf(v0, ma, fmaf(v1, mb_, mc));
            const float vv = fmaf(v0, fmaf(Caa, v0, fmaf(Cab2, v1, Cac2)),
                                  fmaf(v1, fmaf(Cbb, v1, Cbc2), Ccc));
            const float rq = rsqrtf(vv + LN_EPS);
            ((float4*)(buf + rr * 128))[lane] = make_float4(v0, v1, m, rq);
        }
    }
    __syncwarp();

    // ============== stage 1b: accumulate S (lane = dim) ====================
    const float aL = nW1[lane], bL = nW1[HH + lane], cL = nb1[lane];
    const float gL = nlg[lane], lL = nlb[lane];
    float S0 = 0.f, S1 = 0.f, S2 = 0.f, S3 = 0.f;
    #pragma unroll 8
    for (int n = 0; n < NN; n++) {
        {
            const float4 f = ((const float4*)(buf + 0 * 128))[n];
            const float h = fmaf(f.x, aL, fmaf(f.y, bL, cL));
            S0 += fmaxf(fmaf((h - f.z) * f.w, gL, lL), 0.0f);
        }
        {
            const float4 f = ((const float4*)(buf + 1 * 128))[n];
            const float h = fmaf(f.x, aL, fmaf(f.y, bL, cL));
            S1 += fmaxf(fmaf((h - f.z) * f.w, gL, lL), 0.0f);
        }
        {
            const float4 f = ((const float4*)(buf + 2 * 128))[n];
            const float h = fmaf(f.x, aL, fmaf(f.y, bL, cL));
            S2 += fmaxf(fmaf((h - f.z) * f.w, gL, lL), 0.0f);
        }
        {
            const float4 f = ((const float4*)(buf + 3 * 128))[n];
            const float h = fmaf(f.x, aL, fmaf(f.y, bL, cL));
            S3 += fmaxf(fmaf((h - f.z) * f.w, gL, lL), 0.0f);
        }
    }
    __syncwarp();   // stage-1 scratch reads done before reuse

    // ============== self branch (lane = dim, 4 rows) =======================
    float rn0, rn1, rn2, rn3;
    {
        const float spw = sW1[lane], spb = sb1[lane];
        const float spg = slg[lane], spl = slb[lane];
        const float mw = s_selfStats[0], mbb = s_selfStats[1];
        const float c2 = s_selfStats[2], c1 = s_selfStats[3], c0 = s_selfStats[4];
        const float ex0 = expr[rowBase + 0];
        const float ex1 = expr[rowBase + 1];
        const float ex2 = expr[rowBase + 2];
        const float ex3 = expr[rowBase + 3];
        const float rs0 = rsqrtf(fmaf(ex0, fmaf(ex0, c2, c1), c0) + LN_EPS);
        const float rs1 = rsqrtf(fmaf(ex1, fmaf(ex1, c2, c1), c0) + LN_EPS);
        const float rs2 = rsqrtf(fmaf(ex2, fmaf(ex2, c2, c1), c0) + LN_EPS);
        const float rs3 = rsqrtf(fmaf(ex3, fmaf(ex3, c2, c1), c0) + LN_EPS);
        rn0 = fmaxf(fmaf((fmaf(ex0, spw, spb) - fmaf(ex0, mw, mbb)) * rs0, spg, spl), 0.0f);
        rn1 = fmaxf(fmaf((fmaf(ex1, spw, spb) - fmaf(ex1, mw, mbb)) * rs1, spg, spl), 0.0f);
        rn2 = fmaxf(fmaf((fmaf(ex2, spw, spb) - fmaf(ex2, mw, mbb)) * rs2, spg, spl), 0.0f);
        rn3 = fmaxf(fmaf((fmaf(ex3, spw, spb) - fmaf(ex3, mw, mbb)) * rs3, spg, spl), 0.0f);
    }

    // scratch reuse: scrS = buf[0..127], scrR = buf[128..255] (as float4[32])
    float4* scrS = (float4*)buf;
    float4* scrR = (float4*)(buf + 128);
    scrS[lane] = make_float4(S0, S1, S2, S3);
    scrR[lane] = make_float4(rn0, rn1, rn2, rn3);
    __syncwarp();

    // nagg GEMV: xx_k = S @ nW2[:,k] + N*nb2[k]   (4 rows per weight read)
    float xx0, xx1, xx2, xx3;
    {
        const float base = (float)NN * nb2[lane];
        xx0 = base; xx1 = base; xx2 = base; xx3 = base;
    }
    #pragma unroll 8
    for (int j = 0; j < HH; j++) {
        const float4 sv = scrS[j];
        const float w = s_nW2[j * HH + lane];
        xx0 = fmaf(sv.x, w, xx0); xx1 = fmaf(sv.y, w, xx1);
        xx2 = fmaf(sv.z, w, xx2); xx3 = fmaf(sv.w, w, xx3);
    }
    // self GEMV: e_k = rn @ sW2[:,k] + sb2[k]
    float e0, e1, e2, e3;
    {
        const float base = sb2[lane];
        e0 = base; e1 = base; e2 = base; e3 = base;
    }
    #pragma unroll 8
    for (int j = 0; j < HH; j++) {
        const float4 rv = scrR[j];
        const float w = s_sW2[j * HH + lane];
        e0 = fmaf(rv.x, w, e0); e1 = fmaf(rv.y, w, e1);
        e2 = fmaf(rv.z, w, e2); e3 = fmaf(rv.w, w, e3);
    }

    // ============== shared head ===========================================
    // scrX = buf[256..511] (float4[64]): x_j packed for 4 rows
    float4* scrX = (float4*)(buf + 256);
    scrX[lane]      = make_float4(e0, e1, e2, e3);
    scrX[HH + lane] = make_float4(xx0, xx1, xx2, xx3);
    __syncwarp();

    const float2 hbv = *(const float2*)&hb1[2 * lane];
    float y00 = hbv.x, y10 = hbv.y;
    float y01 = hbv.x, y11 = hbv.y;
    float y02 = hbv.x, y12 = hbv.y;
    float y03 = hbv.x, y13 = hbv.y;
    #pragma unroll 8
    for (int j = 0; j < DD; j++) {
        const float4 xv = scrX[j];
        const float2 w = *(const float2*)&s_hW1[j * DD + 2 * lane];
        y00 = fmaf(xv.x, w.x, y00); y10 = fmaf(xv.x, w.y, y10);
        y01 = fmaf(xv.y, w.x, y01); y11 = fmaf(xv.y, w.y, y11);
        y02 = fmaf(xv.z, w.x, y02); y12 = fmaf(xv.z, w.y, y12);
        y03 = fmaf(xv.w, w.x, y03); y13 = fmaf(xv.w, w.y, y13);
    }

    // LN over 64 dims (2 per lane), 4 rows
    float s20 = y00 + y10, q20 = fmaf(y00, y00, y10 * y10);
    float s21 = y01 + y11, q21 = fmaf(y01, y01, y11 * y11);
    float s22 = y02 + y12, q22 = fmaf(y02, y02, y12 * y12);
    float s23 = y03 + y13, q23 = fmaf(y03, y03, y13 * y13);
    #pragma unroll
    for (int ofs = 16; ofs >= 1; ofs >>= 1) {
        s20 += __shfl_xor_sync(FULLMASK, s20, ofs);
        q20 += __shfl_xor_sync(FULLMASK, q20, ofs);
        s21 += __shfl_xor_sync(FULLMASK, s21, ofs);
        q21 += __shfl_xor_sync(FULLMASK, q21, ofs);
        s22 += __shfl_xor_sync(FULLMASK, s22, ofs);
        q22 += __shfl_xor_sync(FULLMASK, q22, ofs);
        s23 += __shfl_xor_sync(FULLMASK, s23, ofs);
        q23 += __shfl_xor_sync(FULLMASK, q23, ofs);
    }
    const float m20 = s20 * (1.0f / DD);
    const float r20 = rsqrtf(fmaf(-m20, m20, q20 * (1.0f / DD)) + LN_EPS);
    const float m21 = s21 * (1.0f / DD);
    const float r21 = rsqrtf(fmaf(-m21, m21, q21 * (1.0f / DD)) + LN_EPS);
    const float m22 = s22 * (1.0f / DD);
    const float r22 = rsqrtf(fmaf(-m22, m22, q22 * (1.0f / DD)) + LN_EPS);
    const float m23 = s23 * (1.0f / DD);
    const float r23 = rsqrtf(fmaf(-m23, m23, q23 * (1.0f / DD)) + LN_EPS);
    const float2 gg = *(const float2*)&hlg[2 * lane];
    const float2 lb = *(const float2*)&hlb[2 * lane];

    // scrY = buf[0..255] (float4[64]) — scrS/scrR fully consumed (sync'd above)
    float4* scrY = (float4*)buf;
    scrY[2 * lane] = make_float4(
        fmaxf(fmaf((y00 - m20) * r20, gg.x, lb.x), 0.0f),
        fmaxf(fmaf((y01 - m21) * r21, gg.x, lb.x), 0.0f),
        fmaxf(fmaf((y02 - m22) * r22, gg.x, lb.x), 0.0f),
        fmaxf(fmaf((y03 - m23) * r23, gg.x, lb.x), 0.0f));
    scrY[2 * lane + 1] = make_float4(
        fmaxf(fmaf((y10 - m20) * r20, gg.y, lb.y), 0.0f),
        fmaxf(fmaf((y11 - m21) * r21, gg.y, lb.y), 0.0f),
        fmaxf(fmaf((y12 - m22) * r22, gg.y, lb.y), 0.0f),
        fmaxf(fmaf((y13 - m23) * r23, gg.y, lb.y), 0.0f));
    __syncwarp();

    // out_k = yn @ hW2[:,k] + hb2[k]
    float o0, o1, o2, o3;
    {
        const float base = hb2[lane];
        o0 = base; o1 = base; o2 = base; o3 = base;
    }
    #pragma unroll 8
    for (int j = 0; j < DD; j++) {
        const float4 yv = scrY[j];
        const float w = s_hW2[j * OO + lane];
        o0 = fmaf(yv.x, w, o0); o1 = fmaf(yv.y, w, o1);
        o2 = fmaf(yv.z, w, o2); o3 = fmaf(yv.w, w, o3);
    }

    // mask + store (4 rows; warp writes 128B contiguous per row)
    if (mask[rowBase + 0] != 0u) o0 = 0.0f;
    if (mask[rowBase + 1] != 0u) o1 = 0.0f;
    if (mask[rowBase + 2] != 0u) o2 = 0.0f;
    if (mask[rowBase + 3] != 0u) o3 = 0.0f;
    out[(size_t)(rowBase + 0) * OO + lane] = o0;
    out[(size_t)(rowBase + 1) * OO + lane] = o1;
    out[(size_t)(rowBase + 2) * OO + lane] = o2;
    out[(size_t)(rowBase + 3) * OO + lane] = o3;
}

// ---------------------------------------------------------------------------
extern "C" void kernel_launch(void* const* d_in, const int* in_sizes, int n_in,
                              void* d_out, int out_size)
{
    (void)in_sizes; (void)n_in; (void)out_size;
    const float* expr          = (const float*)d_in[0];
    const float* neighbors     = (const float*)d_in[1];
    const float* edge          = (const float*)d_in[2];
    const unsigned int* mask   = (const unsigned int*)d_in[3];
    const float* nW1 = (const float*)d_in[4];
    const float* nb1 = (const float*)d_in[5];
    const float* nlg = (const float*)d_in[6];
    const float* nlb = (const float*)d_in[7];
    const float* nW2 = (const float*)d_in[8];
    const float* nb2 = (const float*)d_in[9];
    const float* sW1 = (const float*)d_in[10];
    const float* sb1 = (const float*)d_in[11];
    const float* slg = (const float*)d_in[12];
    const float* slb = (const float*)d_in[13];
    const float* sW2 = (const float*)d_in[14];
    const float* sb2 = (const float*)d_in[15];
    const float* hW1 = (const float*)d_in[16];
    const float* hb1 = (const float*)d_in[17];
    const float* hlg = (const float*)d_in[18];
    const float* hlb = (const float*)d_in[19];
    const float* hW2 = (const float*)d_in[20];
    const float* hb2 = (const float*)d_in[21];
    float* out = (float*)d_out;

    // 16 rows per block -> 2048 blocks of 128 threads (4 rows per warp)
    fused_gnn<<<ROWS / 16, 128>>>(expr, neighbors, edge, mask,
                                  nW1, nb1, nlg, nlb, nW2, nb2,
                                  sW1, sb1, slg, slb, sW2, sb2,
                                  hW1, hb1, hlg, hlb, hW2, hb2, out);
}

// round 15
// speedup vs baseline: 1.2305x; 1.2305x over previous
#include <cuda_runtime.h>

#define BB 8
#define SS 4096
#define NN 32
#define HH 32
#define DD 64
#define OO 32
#define ROWS (BB*SS)        // 32768
#define LN_EPS 1e-5f
#define FULLMASK 0xffffffffu

// Dynamic smem layout (floats):
//   s_nW2   @ 0      (1024)
//   s_sW2   @ 1024   (1024)
//   s_hW1   @ 2048   (4096)
//   s_hW2   @ 6144   (2048)
//   s_nbr   @ 8192   (32*36 = 1152)
//   s_stats @ 9344   (16)   [0..4]=self {mw,mb,c2,c1,c0}, [5..13]=nbr quad form
//   s_buf   @ 9360   (8*512 = 4096)  per-warp scratch
#define SMEM_FLOATS (9360 + 8*512)
#define SMEM_BYTES  (SMEM_FLOATS * 4)

// Block = 256 threads = 8 warps; each warp handles 4 consecutive rows.
// Block covers 32 consecutive rows. Stage 1: lane = neighbor for stats,
// lane = dim for accumulate. GEMV stages: weight LDS amortized over 4 rows,
// x-broadcasts packed as float4 (one wavefront serves all 4 rows).
__global__ __launch_bounds__(256, 4) void fused_gnn(
    const float* __restrict__ expr,        // (B,S)
    const float* __restrict__ neighbors,   // (B,N,S)
    const float* __restrict__ edge,        // (B,S,N)
    const unsigned int* __restrict__ mask, // (B,S) bool widened to 4 bytes
    const float* __restrict__ nW1,         // (2,H)
    const float* __restrict__ nb1,
    const float* __restrict__ nlg,
    const float* __restrict__ nlb,
    const float* __restrict__ nW2,         // (H,H)
    const float* __restrict__ nb2,
    const float* __restrict__ sW1,         // (1,H)
    const float* __restrict__ sb1,
    const float* __restrict__ slg,
    const float* __restrict__ slb,
    const float* __restrict__ sW2,         // (H,H)
    const float* __restrict__ sb2,
    const float* __restrict__ hW1,         // (D,D)
    const float* __restrict__ hb1,
    const float* __restrict__ hlg,
    const float* __restrict__ hlb,
    const float* __restrict__ hW2,         // (D,O)
    const float* __restrict__ hb2,
    float* __restrict__ out)               // (B,S,O)
{
    extern __shared__ float smem[];
    float* s_nW2   = smem;
    float* s_sW2   = smem + 1024;
    float* s_hW1   = smem + 2048;
    float* s_hW2   = smem + 6144;
    float* s_nbr   = smem + 8192;
    float* s_stats = smem + 9344;
    float* s_bufAll= smem + 9360;

    const int tid  = threadIdx.x;
    const int wid  = tid >> 5;
    const int lane = tid & 31;

    // ---- cooperative weight loads ----
    for (int i = tid; i < HH * HH; i += 256) s_nW2[i] = nW2[i];
    for (int i = tid; i < HH * HH; i += 256) s_sW2[i] = sW2[i];
    for (int i = tid; i < DD * DD; i += 256) s_hW1[i] = hW1[i];
    for (int i = tid; i < DD * OO; i += 256) s_hW2[i] = hW2[i];

    // ---- warp 0: self-branch LN stats (var(ex) = c2 ex^2 + c1 ex + c0) ----
    if (wid == 0) {
        const float w  = sW1[lane];
        const float bb = sb1[lane];
        float sw = w, sb_ = bb, sww = w * w, swb = w * bb, sbb = bb * bb;
        #pragma unroll
        for (int ofs = 16; ofs >= 1; ofs >>= 1) {
            sw  += __shfl_xor_sync(FULLMASK, sw,  ofs);
            sb_ += __shfl_xor_sync(FULLMASK, sb_, ofs);
            sww += __shfl_xor_sync(FULLMASK, sww, ofs);
            swb += __shfl_xor_sync(FULLMASK, swb, ofs);
            sbb += __shfl_xor_sync(FULLMASK, sbb, ofs);
        }
        if (lane == 0) {
            const float mw = sw * (1.0f / HH), mb = sb_ * (1.0f / HH);
            s_stats[0] = mw;
            s_stats[1] = mb;
            s_stats[2] = fmaf(-mw, mw, sww * (1.0f / HH));
            s_stats[3] = 2.0f * fmaf(-mw, mb, swb * (1.0f / HH));
            s_stats[4] = fmaf(-mb, mb, sbb * (1.0f / HH));
        }
    }
    // ---- warp 1: neighbor-branch LN stats (quadratic form in v0,v1) ----
    if (wid == 1) {
        const float a = nW1[lane], b = nW1[HH + lane], c = nb1[lane];
        float sa = a, sb_ = b, sc = c;
        float saa = a * a, sbb = b * b, scc = c * c;
        float sab = a * b, sac = a * c, sbc = b * c;
        #pragma unroll
        for (int ofs = 16; ofs >= 1; ofs >>= 1) {
            sa  += __shfl_xor_sync(FULLMASK, sa,  ofs);
            sb_ += __shfl_xor_sync(FULLMASK, sb_, ofs);
            sc  += __shfl_xor_sync(FULLMASK, sc,  ofs);
            saa += __shfl_xor_sync(FULLMASK, saa, ofs);
            sbb += __shfl_xor_sync(FULLMASK, sbb, ofs);
            scc += __shfl_xor_sync(FULLMASK, scc, ofs);
            sab += __shfl_xor_sync(FULLMASK, sab, ofs);
            sac += __shfl_xor_sync(FULLMASK, sac, ofs);
            sbc += __shfl_xor_sync(FULLMASK, sbc, ofs);
        }
        if (lane == 0) {
            const float ma = sa * (1.0f / HH), mb = sb_ * (1.0f / HH), mc = sc * (1.0f / HH);
            s_stats[5] = ma; s_stats[6] = mb; s_stats[7] = mc;
            s_stats[8]  = fmaf(-ma, ma, saa * (1.0f / HH));           // Caa
            s_stats[9]  = fmaf(-mb, mb, sbb * (1.0f / HH));           // Cbb
            s_stats[10] = fmaf(-mc, mc, scc * (1.0f / HH));           // Ccc
            s_stats[11] = 2.0f * fmaf(-ma, mb, sab * (1.0f / HH));    // Cab2
            s_stats[12] = 2.0f * fmaf(-ma, mc, sac * (1.0f / HH));    // Cac2
            s_stats[13] = 2.0f * fmaf(-mb, mc, sbc * (1.0f / HH));    // Cbc2
        }
    }

    // ---- stage neighbor tile: rows [r0, r0+32) need neighbors[b][:][s0..s0+31]
    const int r0 = blockIdx.x * 32;
    const int b  = r0 >> 12;
    const int s0 = r0 & (SS - 1);
    {
        const int n  = tid >> 3;              // 0..31
        const int sl = (tid & 7) * 4;         // 0,4,..,28
        const float4 v = *(const float4*)(neighbors + (size_t)b * (NN * SS)
                                          + (size_t)n * SS + s0 + sl);
        *(float4*)&s_nbr[n * 36 + sl] = v;
    }
    __syncthreads();

    const int rowBase = r0 + wid * 4;         // rows rowBase..rowBase+3
    float* buf = s_bufAll + wid * 512;

    // ============== stage 1a: per-neighbor LN stats (lane = neighbor) ======
    {
        // one LDS.128: v0 for this lane's neighbor, this warp's 4 rows.
        // stride 36 floats -> bank = 4*lane mod 32, distinct within each
        // 8-lane float4 phase: conflict-free.
        const float4 v0v = *(const float4*)&s_nbr[lane * 36 + wid * 4];
        const float v0r[4] = {v0v.x, v0v.y, v0v.z, v0v.w};
        const float ma = s_stats[5], mb_ = s_stats[6], mc = s_stats[7];
        const float Caa = s_stats[8], Cbb = s_stats[9], Ccc = s_stats[10];
        const float Cab2 = s_stats[11], Cac2 = s_stats[12], Cbc2 = s_stats[13];
        #pragma unroll
        for (int rr = 0; rr < 4; rr++) {
            const float v0 = v0r[rr];
            const float v1 = edge[(size_t)(rowBase + rr) * NN + lane];
            const float m  = fmaf(v0, ma, fmaf(v1, mb_, mc));
            const float vv = fmaf(v0, fmaf(Caa, v0, fmaf(Cab2, v1, Cac2)),
                                  fmaf(v1, fmaf(Cbb, v1, Cbc2), Ccc));
            const float rq = rsqrtf(vv + LN_EPS);
            ((float4*)(buf + rr * 128))[lane] = make_float4(v0, v1, m, rq);
        }
    }
    __syncwarp();

    // ============== stage 1b: accumulate S (lane = dim) ====================
    const float aL = nW1[lane], bL = nW1[HH + lane], cL = nb1[lane];
    const float gL = nlg[lane], lL = nlb[lane];
    float S0 = 0.f, S1 = 0.f, S2 = 0.f, S3 = 0.f;
    #pragma unroll 8
    for (int n = 0; n < NN; n++) {
        {
            const float4 f = ((const float4*)(buf + 0 * 128))[n];
            const float h = fmaf(f.x, aL, fmaf(f.y, bL, cL));
            S0 += fmaxf(fmaf((h - f.z) * f.w, gL, lL), 0.0f);
        }
        {
            const float4 f = ((const float4*)(buf + 1 * 128))[n];
            const float h = fmaf(f.x, aL, fmaf(f.y, bL, cL));
            S1 += fmaxf(fmaf((h - f.z) * f.w, gL, lL), 0.0f);
        }
        {
            const float4 f = ((const float4*)(buf + 2 * 128))[n];
            const float h = fmaf(f.x, aL, fmaf(f.y, bL, cL));
            S2 += fmaxf(fmaf((h - f.z) * f.w, gL, lL), 0.0f);
        }
        {
            const float4 f = ((const float4*)(buf + 3 * 128))[n];
            const float h = fmaf(f.x, aL, fmaf(f.y, bL, cL));
            S3 += fmaxf(fmaf((h - f.z) * f.w, gL, lL), 0.0f);
        }
    }
    __syncwarp();   // stage-1 scratch reads done before reuse

    // ============== self branch (lane = dim, 4 rows) =======================
    float rn0, rn1, rn2, rn3;
    {
        const float spw = sW1[lane], spb = sb1[lane];
        const float spg = slg[lane], spl = slb[lane];
        const float mw = s_stats[0], mbb = s_stats[1];
        const float c2 = s_stats[2], c1 = s_stats[3], c0 = s_stats[4];
        const float ex0 = expr[rowBase + 0];
        const float ex1 = expr[rowBase + 1];
        const float ex2 = expr[rowBase + 2];
        const float ex3 = expr[rowBase + 3];
        const float rs0 = rsqrtf(fmaf(ex0, fmaf(ex0, c2, c1), c0) + LN_EPS);
        const float rs1 = rsqrtf(fmaf(ex1, fmaf(ex1, c2, c1), c0) + LN_EPS);
        const float rs2 = rsqrtf(fmaf(ex2, fmaf(ex2, c2, c1), c0) + LN_EPS);
        const float rs3 = rsqrtf(fmaf(ex3, fmaf(ex3, c2, c1), c0) + LN_EPS);
        rn0 = fmaxf(fmaf((fmaf(ex0, spw, spb) - fmaf(ex0, mw, mbb)) * rs0, spg, spl), 0.0f);
        rn1 = fmaxf(fmaf((fmaf(ex1, spw, spb) - fmaf(ex1, mw, mbb)) * rs1, spg, spl), 0.0f);
        rn2 = fmaxf(fmaf((fmaf(ex2, spw, spb) - fmaf(ex2, mw, mbb)) * rs2, spg, spl), 0.0f);
        rn3 = fmaxf(fmaf((fmaf(ex3, spw, spb) - fmaf(ex3, mw, mbb)) * rs3, spg, spl), 0.0f);
    }

    // scratch reuse: scrS = buf[0..127], scrR = buf[128..255] (as float4[32])
    float4* scrS = (float4*)buf;
    float4* scrR = (float4*)(buf + 128);
    scrS[lane] = make_float4(S0, S1, S2, S3);
    scrR[lane] = make_float4(rn0, rn1, rn2, rn3);
    __syncwarp();

    // nagg GEMV: xx_k = S @ nW2[:,k] + N*nb2[k]   (4 rows per weight read)
    float xx0, xx1, xx2, xx3;
    {
        const float base = (float)NN * nb2[lane];
        xx0 = base; xx1 = base; xx2 = base; xx3 = base;
    }
    #pragma unroll 8
    for (int j = 0; j < HH; j++) {
        const float4 sv = scrS[j];
        const float w = s_nW2[j * HH + lane];
        xx0 = fmaf(sv.x, w, xx0); xx1 = fmaf(sv.y, w, xx1);
        xx2 = fmaf(sv.z, w, xx2); xx3 = fmaf(sv.w, w, xx3);
    }
    // self GEMV: e_k = rn @ sW2[:,k] + sb2[k]
    float e0, e1, e2, e3;
    {
        const float base = sb2[lane];
        e0 = base; e1 = base; e2 = base; e3 = base;
    }
    #pragma unroll 8
    for (int j = 0; j < HH; j++) {
        const float4 rv = scrR[j];
        const float w = s_sW2[j * HH + lane];
        e0 = fmaf(rv.x, w, e0); e1 = fmaf(rv.y, w, e1);
        e2 = fmaf(rv.z, w, e2); e3 = fmaf(rv.w, w, e3);
    }

    // ============== shared head ===========================================
    // scrX = buf[256..511] (float4[64]): x_j packed for 4 rows
    float4* scrX = (float4*)(buf + 256);
    scrX[lane]      = make_float4(e0, e1, e2, e3);
    scrX[HH + lane] = make_float4(xx0, xx1, xx2, xx3);
    __syncwarp();

    const float2 hbv = *(const float2*)&hb1[2 * lane];
    float y00 = hbv.x, y10 = hbv.y;
    float y01 = hbv.x, y11 = hbv.y;
    float y02 = hbv.x, y12 = hbv.y;
    float y03 = hbv.x, y13 = hbv.y;
    #pragma unroll 8
    for (int j = 0; j < DD; j++) {
        const float4 xv = scrX[j];
        const float2 w = *(const float2*)&s_hW1[j * DD + 2 * lane];
        y00 = fmaf(xv.x, w.x, y00); y10 = fmaf(xv.x, w.y, y10);
        y01 = fmaf(xv.y, w.x, y01); y11 = fmaf(xv.y, w.y, y11);
        y02 = fmaf(xv.z, w.x, y02); y12 = fmaf(xv.z, w.y, y12);
        y03 = fmaf(xv.w, w.x, y03); y13 = fmaf(xv.w, w.y, y13);
    }

    // LN over 64 dims (2 per lane), 4 rows
    float s20 = y00 + y10, q20 = fmaf(y00, y00, y10 * y10);
    float s21 = y01 + y11, q21 = fmaf(y01, y01, y11 * y11);
    float s22 = y02 + y12, q22 = fmaf(y02, y02, y12 * y12);
    float s23 = y03 + y13, q23 = fmaf(y03, y03, y13 * y13);
    #pragma unroll
    for (int ofs = 16; ofs >= 1; ofs >>= 1) {
        s20 += __shfl_xor_sync(FULLMASK, s20, ofs);
        q20 += __shfl_xor_sync(FULLMASK, q20, ofs);
        s21 += __shfl_xor_sync(FULLMASK, s21, ofs);
        q21 += __shfl_xor_sync(FULLMASK, q21, ofs);
        s22 += __shfl_xor_sync(FULLMASK, s22, ofs);
        q22 += __shfl_xor_sync(FULLMASK, q22, ofs);
        s23 += __shfl_xor_sync(FULLMASK, s23, ofs);
        q23 += __shfl_xor_sync(FULLMASK, q23, ofs);
    }
    const float m20 = s20 * (1.0f / DD);
    const float r20 = rsqrtf(fmaf(-m20, m20, q20 * (1.0f / DD)) + LN_EPS);
    const float m21 = s21 * (1.0f / DD);
    const float r21 = rsqrtf(fmaf(-m21, m21, q21 * (1.0f / DD)) + LN_EPS);
    const float m22 = s22 * (1.0f / DD);
    const float r22 = rsqrtf(fmaf(-m22, m22, q22 * (1.0f / DD)) + LN_EPS);
    const float m23 = s23 * (1.0f / DD);
    const float r23 = rsqrtf(fmaf(-m23, m23, q23 * (1.0f / DD)) + LN_EPS);
    const float2 gg = *(const float2*)&hlg[2 * lane];
    const float2 lb = *(const float2*)&hlb[2 * lane];

    // scrY = buf[0..255] (float4[64]) — scrS/scrR fully consumed (sync'd above)
    float4* scrY = (float4*)buf;
    scrY[2 * lane] = make_float4(
        fmaxf(fmaf((y00 - m20) * r20, gg.x, lb.x), 0.0f),
        fmaxf(fmaf((y01 - m21) * r21, gg.x, lb.x), 0.0f),
        fmaxf(fmaf((y02 - m22) * r22, gg.x, lb.x), 0.0f),
        fmaxf(fmaf((y03 - m23) * r23, gg.x, lb.x), 0.0f));
    scrY[2 * lane + 1] = make_float4(
        fmaxf(fmaf((y10 - m20) * r20, gg.y, lb.y), 0.0f),
        fmaxf(fmaf((y11 - m21) * r21, gg.y, lb.y), 0.0f),
        fmaxf(fmaf((y12 - m22) * r22, gg.y, lb.y), 0.0f),
        fmaxf(fmaf((y13 - m23) * r23, gg.y, lb.y), 0.0f));
    __syncwarp();

    // out_k = yn @ hW2[:,k] + hb2[k]
    float o0, o1, o2, o3;
    {
        const float base = hb2[lane];
        o0 = base; o1 = base; o2 = base; o3 = base;
    }
    #pragma unroll 8
    for (int j = 0; j < DD; j++) {
        const float4 yv = scrY[j];
        const float w = s_hW2[j * OO + lane];
        o0 = fmaf(yv.x, w, o0); o1 = fmaf(yv.y, w, o1);
        o2 = fmaf(yv.z, w, o2); o3 = fmaf(yv.w, w, o3);
    }

    // mask + store (4 rows; warp writes 128B contiguous per row)
    if (mask[rowBase + 0] != 0u) o0 = 0.0f;
    if (mask[rowBase + 1] != 0u) o1 = 0.0f;
    if (mask[rowBase + 2] != 0u) o2 = 0.0f;
    if (mask[rowBase + 3] != 0u) o3 = 0.0f;
    out[(size_t)(rowBase + 0) * OO + lane] = o0;
    out[(size_t)(rowBase + 1) * OO + lane] = o1;
    out[(size_t)(rowBase + 2) * OO + lane] = o2;
    out[(size_t)(rowBase + 3) * OO + lane] = o3;
}

// ---------------------------------------------------------------------------
extern "C" void kernel_launch(void* const* d_in, const int* in_sizes, int n_in,
                              void* d_out, int out_size)
{
    (void)in_sizes; (void)n_in; (void)out_size;
    const float* expr          = (const float*)d_in[0];
    const float* neighbors     = (const float*)d_in[1];
    const float* edge          = (const float*)d_in[2];
    const unsigned int* mask   = (const unsigned int*)d_in[3];
    const float* nW1 = (const float*)d_in[4];
    const float* nb1 = (const float*)d_in[5];
    const float* nlg = (const float*)d_in[6];
    const float* nlb = (const float*)d_in[7];
    const float* nW2 = (const float*)d_in[8];
    const float* nb2 = (const float*)d_in[9];
    const float* sW1 = (const float*)d_in[10];
    const float* sb1 = (const float*)d_in[11];
    const float* slg = (const float*)d_in[12];
    const float* slb = (const float*)d_in[13];
    const float* sW2 = (const float*)d_in[14];
    const float* sb2 = (const float*)d_in[15];
    const float* hW1 = (const float*)d_in[16];
    const float* hb1 = (const float*)d_in[17];
    const float* hlg = (const float*)d_in[18];
    const float* hlb = (const float*)d_in[19];
    const float* hW2 = (const float*)d_in[20];
    const float* hb2 = (const float*)d_in[21];
    float* out = (float*)d_out;

    // Opt in to >48KB dynamic smem (host-side attribute set, idempotent,
    // executes immediately — legal under graph capture).
    cudaFuncSetAttribute(fused_gnn, cudaFuncAttributeMaxDynamicSharedMemorySize,
                         SMEM_BYTES);

    // 32 rows per block -> 1024 blocks of 256 threads (4 rows per warp)
    fused_gnn<<<ROWS / 32, 256, SMEM_BYTES>>>(expr, neighbors, edge, mask,
                                              nW1, nb1, nlg, nlb, nW2, nb2,
                                              sW1, sb1, slg, slb, sW2, sb2,
                                              hW1, hb1, hlg, hlb, hW2, hb2, out);
}